// round 2
// baseline (speedup 1.0000x reference)
#include <cuda_runtime.h>
#include <math.h>

#define B_     64
#define F_     4097
#define FCL_   65
#define FL_    64
#define IR_    129
#define CONV_  192
#define OUT_S  262144
#define NFRB   32          // frames per block
#define NWARP  8
#define FPW    4           // frames per warp
#define ACCLEN 2176        // (NFRB-1)*64 + 192

// Accurate trig / window tables, filled in double precision each call.
__device__ float g_c65[66];
__device__ float g_s65[66];
__device__ float g_win[130];

__global__ void init_tables_k() {
    int i = threadIdx.x;
    const double TH = 2.0 * 3.141592653589793238462643 / 129.0;
    if (i < 66) {
        g_c65[i] = (float)cos(TH * (double)i);
        g_s65[i] = (float)sin(TH * (double)i);
    }
    if (i < 130) {
        g_win[i] = (float)(0.5 - 0.5 * cos(TH * (double)i));
    }
}

__global__ void zero_out_k(float4* __restrict__ out, int n4) {
    int i = blockIdx.x * blockDim.x + threadIdx.x;
    float4 z = make_float4(0.f, 0.f, 0.f, 0.f);
    for (; i < n4; i += gridDim.x * blockDim.x) out[i] = z;
}

__device__ __forceinline__ float msig(float x) {
    // 2 * sigmoid(x)^ln(10) + 1e-7 ; x in [-1,1] so sigmoid in [0.27,0.73]
    float sg = 1.0f / (1.0f + __expf(-x));
    return 2.0f * __powf(sg, 2.302585092994046f) + 1e-7f;
}

__global__ __launch_bounds__(256) void fn_main(
        const float* __restrict__ coeff,   // (B, F, 65)
        const float* __restrict__ noise,   // (B, F, 64)
        float* __restrict__ out)           // (B, 262144)
{
    __shared__ float cosS[66], sinS[66], winS[130];
    __shared__ float wirb[NWARP][256];   // padded: zeros [0,63] & [193,255], wir at [64..192]
    __shared__ float xsb[NWARP][64];
    __shared__ float sbuf[NWARP][66];
    __shared__ float outb[NFRB][CONV_];  // per-frame conv results

    const int tid = threadIdx.x;
    const int w   = tid >> 5;
    const int l   = tid & 31;
    const int q   = blockIdx.x;          // 0..127 (frames 0..4095; frame 4096 never contributes)
    const int b   = blockIdx.y;
    const int f0  = q * NFRB;

    // Stage tables; zero wir buffers (padding regions stay zero for all frames).
    for (int i = tid; i < 66;  i += 256) { cosS[i] = g_c65[i]; sinS[i] = g_s65[i]; }
    for (int i = tid; i < 130; i += 256) winS[i] = g_win[i];
    for (int i = tid; i < NWARP * 256; i += 256) ((float*)wirb)[i] = 0.f;
    __syncthreads();

    // Per-lane rotation seeds: lane handles t1 = l+1 (1..32), t2 = l+33 (33..64); t=0 shared.
    const int   t1  = l + 1,  t2 = l + 33;
    const float rc1 = cosS[t1], rs1 = sinS[t1];
    const float rc2 = cosS[t2], rs2 = sinS[t2];
    const float w1p = winS[64 + t1], w1m = winS[64 - t1];
    const float w2p = winS[64 + t2], w2m = winS[64 - t2];
    const float wc  = winS[64];

    for (int ff = 0; ff < FPW; ff++) {
        const int fi = ff * NWARP + w;          // 0..31, unique per (ff,w)
        const int f  = f0 + fi;                 // < 4097 always (q<=127 -> f<=4095)

        // ---- load coefficients + noise, apply modified sigmoid / rescale ----
        const float* cp = coeff + ((size_t)b * F_ + f) * FCL_;
        const float* np = noise + ((size_t)b * F_ + f) * FL_;
        sbuf[w][l]      = msig(cp[l]);
        sbuf[w][l + 32] = msig(cp[l + 32]);
        if (l == 0) sbuf[w][64] = msig(cp[64]);
        xsb[w][l]       = 2.f * np[l]      - 1.f;
        xsb[w][l + 32]  = 2.f * np[l + 32] - 1.f;
        __syncwarp();

        // ---- cosine transform (irfft of real spectrum) via stable rotation ----
        // zp[t] = (s0 + 2*sum_{k=1..64} s_k cos(2pi k t/129)) / 129, t = 0..64
        float c1 = rc1, s1 = rs1, c2 = rc2, s2 = rs2;
        float ac0 = 0.f, ac1 = 0.f, ac2 = 0.f;
        const float s0v = sbuf[w][0];
        #pragma unroll 8
        for (int k = 1; k <= 64; k++) {
            const float sk = sbuf[w][k];
            ac0 += sk;
            ac1 += sk * c1;
            ac2 += sk * c2;
            const float nc1 = c1 * rc1 - s1 * rs1;
            const float ns1 = s1 * rc1 + c1 * rs1;
            c1 = nc1; s1 = ns1;
            const float nc2 = c2 * rc2 - s2 * rs2;
            const float ns2 = s2 * rc2 + c2 * rs2;
            c2 = nc2; s2 = ns2;
        }
        const float SCL = 1.0f / 129.0f;
        const float zp0 = (s0v + 2.f * ac0) * SCL;
        const float zp1 = (s0v + 2.f * ac1) * SCL;
        const float zp2 = (s0v + 2.f * ac2) * SCL;

        // ---- windowed linear-phase IR into padded buffer ----
        // lp[j] = zp[(j-64) mod 129]; zp symmetric -> lp[64+d]=lp[64-d]=zp[d]
        float* wb = wirb[w];
        wb[128 + t1] = w1p * zp1;   // j = 64+t1
        wb[128 - t1] = w1m * zp1;   // j = 64-t1
        wb[128 + t2] = w2p * zp2;   // j = 64+t2
        wb[128 - t2] = w2m * zp2;   // j = 64-t2
        if (l == 0) wb[128] = wc * zp0;   // j = 64
        __syncwarp();

        // ---- linear convolution: out[t] = sum_tau x[tau] * wir[t-tau], t=0..191 ----
        float a0 = 0.f, a1 = 0.f, a2 = 0.f, a3 = 0.f, a4 = 0.f, a5 = 0.f;
        #pragma unroll 4
        for (int tau = 0; tau < 64; tau++) {
            const float xv = xsb[w][tau];
            const float* wp = &wb[64 + l - tau];   // index in [1,255]; zeros outside IR
            a0 += xv * wp[0];
            a1 += xv * wp[32];
            a2 += xv * wp[64];
            a3 += xv * wp[96];
            a4 += xv * wp[128];
            a5 += xv * wp[160];
        }
        float* ob = outb[fi];
        ob[l]       = a0;
        ob[l + 32]  = a1;
        ob[l + 64]  = a2;
        ob[l + 96]  = a3;
        ob[l + 128] = a4;
        ob[l + 160] = a5;
        __syncwarp();   // all lanes done with sbuf/xsb/wirb before next frame reuses them
    }

    __syncthreads();

    // ---- overlap-add: gather up to 3 contributing frames per output sample ----
    const size_t rowb = (size_t)b * OUT_S;
    const int gb = f0 * FL_;                  // q * 2048
    for (int p = tid; p < ACCLEN; p += 256) {
        const int P = gb + p;
        if (P >= OUT_S) continue;
        const int fhi = p >> 6;
        const int t0  = p & 63;
        float v = 0.f;
        if (fhi < NFRB)                 v += outb[fhi][t0];
        if (fhi >= 1 && fhi - 1 < NFRB) v += outb[fhi - 1][t0 + 64];
        if (fhi >= 2 && fhi - 2 < NFRB) v += outb[fhi - 2][t0 + 128];
        if (p >= 128 && p < 2048) out[rowb + P] = v;        // exclusively owned
        else                      atomicAdd(&out[rowb + P], v);  // block boundary
    }
}

extern "C" void kernel_launch(void* const* d_in, const int* in_sizes, int n_in,
                              void* d_out, int out_size) {
    const float* coeff = (const float*)d_in[0];
    const float* noise = (const float*)d_in[1];
    float* out = (float*)d_out;

    init_tables_k<<<1, 130>>>();
    zero_out_k<<<4096, 256>>>((float4*)out, (B_ * OUT_S) / 4);
    dim3 grid(128, B_);   // 128 frame-blocks x 64 batch rows; frame 4096 never reaches output
    fn_main<<<grid, 256>>>(coeff, noise, out);
}

// round 3
// speedup vs baseline: 1.0004x; 1.0004x over previous
#include <cuda_runtime.h>
#include <math.h>

#define B_     64
#define F_     4097
#define FCL_   65
#define FL_    64
#define IR_    129
#define CONV_  192
#define OUT_S  262144
#define NFRB   32          // frames per block
#define NWARP  8
#define FPW    4           // frames per warp
#define ACCLEN 2176        // (NFRB-1)*64 + 192

// Accurate trig / window tables, filled in double precision each call.
__device__ float g_c65[66];
__device__ float g_s65[66];
__device__ float g_win[130];

__global__ void init_tables_k() {
    int i = threadIdx.x;
    const double TH = 2.0 * 3.141592653589793238462643 / 129.0;
    if (i < 66) {
        g_c65[i] = (float)cos(TH * (double)i);
        g_s65[i] = (float)sin(TH * (double)i);
    }
    if (i < 130) {
        g_win[i] = (float)(0.5 - 0.5 * cos(TH * (double)i));
    }
}

__global__ void zero_out_k(float4* __restrict__ out, int n4) {
    int i = blockIdx.x * blockDim.x + threadIdx.x;
    float4 z = make_float4(0.f, 0.f, 0.f, 0.f);
    for (; i < n4; i += gridDim.x * blockDim.x) out[i] = z;
}

__device__ __forceinline__ float msig(float x) {
    // 2 * sigmoid(x)^ln(10) + 1e-7 ; x in [-1,1] so sigmoid in [0.27,0.73]
    float sg = 1.0f / (1.0f + __expf(-x));
    return 2.0f * __powf(sg, 2.302585092994046f) + 1e-7f;
}

__global__ __launch_bounds__(256) void fn_main(
        const float* __restrict__ coeff,   // (B, F, 65)
        const float* __restrict__ noise,   // (B, F, 64)
        float* __restrict__ out)           // (B, 262144)
{
    __shared__ float cosS[66], sinS[66], winS[130];
    __shared__ float wirb[NWARP][256];   // padded: zeros [0,63] & [193,255], wir at [64..192]
    __shared__ float xsb[NWARP][64];
    __shared__ float sbuf[NWARP][66];
    __shared__ float outb[NFRB][CONV_];  // per-frame conv results

    const int tid = threadIdx.x;
    const int w   = tid >> 5;
    const int l   = tid & 31;
    const int q   = blockIdx.x;          // 0..127 (frames 0..4095; frame 4096 never contributes)
    const int b   = blockIdx.y;
    const int f0  = q * NFRB;

    // Stage tables; zero wir buffers (padding regions stay zero for all frames).
    for (int i = tid; i < 66;  i += 256) { cosS[i] = g_c65[i]; sinS[i] = g_s65[i]; }
    for (int i = tid; i < 130; i += 256) winS[i] = g_win[i];
    for (int i = tid; i < NWARP * 256; i += 256) ((float*)wirb)[i] = 0.f;
    __syncthreads();

    // Per-lane rotation seeds: lane handles t1 = l+1 (1..32), t2 = l+33 (33..64); t=0 shared.
    const int   t1  = l + 1,  t2 = l + 33;
    const float rc1 = cosS[t1], rs1 = sinS[t1];
    const float rc2 = cosS[t2], rs2 = sinS[t2];
    const float w1p = winS[64 + t1], w1m = winS[64 - t1];
    const float w2p = winS[64 + t2], w2m = winS[64 - t2];
    const float wc  = winS[64];

    for (int ff = 0; ff < FPW; ff++) {
        const int fi = ff * NWARP + w;          // 0..31, unique per (ff,w)
        const int f  = f0 + fi;                 // < 4097 always (q<=127 -> f<=4095)

        // ---- load coefficients + noise, apply modified sigmoid / rescale ----
        const float* cp = coeff + ((size_t)b * F_ + f) * FCL_;
        const float* np = noise + ((size_t)b * F_ + f) * FL_;
        sbuf[w][l]      = msig(cp[l]);
        sbuf[w][l + 32] = msig(cp[l + 32]);
        if (l == 0) sbuf[w][64] = msig(cp[64]);
        xsb[w][l]       = 2.f * np[l]      - 1.f;
        xsb[w][l + 32]  = 2.f * np[l + 32] - 1.f;
        __syncwarp();

        // ---- cosine transform (irfft of real spectrum) via stable rotation ----
        // zp[t] = (s0 + 2*sum_{k=1..64} s_k cos(2pi k t/129)) / 129, t = 0..64
        float c1 = rc1, s1 = rs1, c2 = rc2, s2 = rs2;
        float ac0 = 0.f, ac1 = 0.f, ac2 = 0.f;
        const float s0v = sbuf[w][0];
        #pragma unroll 8
        for (int k = 1; k <= 64; k++) {
            const float sk = sbuf[w][k];
            ac0 += sk;
            ac1 += sk * c1;
            ac2 += sk * c2;
            const float nc1 = c1 * rc1 - s1 * rs1;
            const float ns1 = s1 * rc1 + c1 * rs1;
            c1 = nc1; s1 = ns1;
            const float nc2 = c2 * rc2 - s2 * rs2;
            const float ns2 = s2 * rc2 + c2 * rs2;
            c2 = nc2; s2 = ns2;
        }
        const float SCL = 1.0f / 129.0f;
        const float zp0 = (s0v + 2.f * ac0) * SCL;
        const float zp1 = (s0v + 2.f * ac1) * SCL;
        const float zp2 = (s0v + 2.f * ac2) * SCL;

        // ---- windowed linear-phase IR into padded buffer ----
        // lp[j] = zp[(j-64) mod 129]; zp symmetric -> lp[64+d]=lp[64-d]=zp[d]
        float* wb = wirb[w];
        wb[128 + t1] = w1p * zp1;   // j = 64+t1
        wb[128 - t1] = w1m * zp1;   // j = 64-t1
        wb[128 + t2] = w2p * zp2;   // j = 64+t2
        wb[128 - t2] = w2m * zp2;   // j = 64-t2
        if (l == 0) wb[128] = wc * zp0;   // j = 64
        __syncwarp();

        // ---- linear convolution: out[t] = sum_tau x[tau] * wir[t-tau], t=0..191 ----
        float a0 = 0.f, a1 = 0.f, a2 = 0.f, a3 = 0.f, a4 = 0.f, a5 = 0.f;
        #pragma unroll 4
        for (int tau = 0; tau < 64; tau++) {
            const float xv = xsb[w][tau];
            const float* wp = &wb[64 + l - tau];   // index in [1,255]; zeros outside IR
            a0 += xv * wp[0];
            a1 += xv * wp[32];
            a2 += xv * wp[64];
            a3 += xv * wp[96];
            a4 += xv * wp[128];
            a5 += xv * wp[160];
        }
        float* ob = outb[fi];
        ob[l]       = a0;
        ob[l + 32]  = a1;
        ob[l + 64]  = a2;
        ob[l + 96]  = a3;
        ob[l + 128] = a4;
        ob[l + 160] = a5;
        __syncwarp();   // all lanes done with sbuf/xsb/wirb before next frame reuses them
    }

    __syncthreads();

    // ---- overlap-add: gather up to 3 contributing frames per output sample ----
    const size_t rowb = (size_t)b * OUT_S;
    const int gb = f0 * FL_;                  // q * 2048
    for (int p = tid; p < ACCLEN; p += 256) {
        const int P = gb + p;
        if (P >= OUT_S) continue;
        const int fhi = p >> 6;
        const int t0  = p & 63;
        float v = 0.f;
        if (fhi < NFRB)                 v += outb[fhi][t0];
        if (fhi >= 1 && fhi - 1 < NFRB) v += outb[fhi - 1][t0 + 64];
        if (fhi >= 2 && fhi - 2 < NFRB) v += outb[fhi - 2][t0 + 128];
        if (p >= 128 && p < 2048) out[rowb + P] = v;        // exclusively owned
        else                      atomicAdd(&out[rowb + P], v);  // block boundary
    }
}

extern "C" void kernel_launch(void* const* d_in, const int* in_sizes, int n_in,
                              void* d_out, int out_size) {
    const float* coeff = (const float*)d_in[0];
    const float* noise = (const float*)d_in[1];
    float* out = (float*)d_out;

    init_tables_k<<<1, 130>>>();
    zero_out_k<<<4096, 256>>>((float4*)out, (B_ * OUT_S) / 4);
    dim3 grid(128, B_);   // 128 frame-blocks x 64 batch rows; frame 4096 never reaches output
    fn_main<<<grid, 256>>>(coeff, noise, out);
}

// round 4
// speedup vs baseline: 1.3377x; 1.3371x over previous
#include <cuda_runtime.h>
#include <math.h>

typedef unsigned long long ull;
struct __align__(16) ULL2 { ull x, y; };

#define B_     64
#define F_     4097
#define FCL_   65
#define FL_    64
#define OUT_S  262144
#define NFRB   32          // frames per block
#define NWARP  8
#define ACCLEN 2176        // (NFRB-1)*64 + 192

// ---------------- packed f32x2 helpers (Blackwell FFMA2 path) ----------------
__device__ __forceinline__ ull fma2_(ull a, ull b, ull c) {
    ull d; asm("fma.rn.f32x2 %0,%1,%2,%3;" : "=l"(d) : "l"(a), "l"(b), "l"(c)); return d;
}
__device__ __forceinline__ ull add2_(ull a, ull b) {
    ull d; asm("add.rn.f32x2 %0,%1,%2;" : "=l"(d) : "l"(a), "l"(b)); return d;
}
__device__ __forceinline__ ull mul2_(ull a, ull b) {
    ull d; asm("mul.rn.f32x2 %0,%1,%2;" : "=l"(d) : "l"(a), "l"(b)); return d;
}
__device__ __forceinline__ ull dup_(float x) {
    ull d; unsigned r = __float_as_uint(x);
    asm("mov.b64 %0,{%1,%1};" : "=l"(d) : "r"(r)); return d;
}
__device__ __forceinline__ ull pk_(float lo, float hi) {
    ull d; asm("mov.b64 %0,{%1,%2};" : "=l"(d) : "r"(__float_as_uint(lo)), "r"(__float_as_uint(hi))); return d;
}
__device__ __forceinline__ void unpk_(ull v, float& lo, float& hi) {
    unsigned a, b; asm("mov.b64 {%0,%1},%2;" : "=r"(a), "=r"(b) : "l"(v));
    lo = __uint_as_float(a); hi = __uint_as_float(b);
}

// ---------------- accurate tables (double precision, built on device) ----------------
__device__ float2 g_cosP[64 * 32];   // [k-1][l] = (cos(th*k*(l+1)), cos(th*k*(l+33)))
__device__ float  g_win[130];

__global__ void init_tables_k() {
    int i = blockIdx.x * blockDim.x + threadIdx.x;
    const double TH = 2.0 * 3.141592653589793238462643 / 129.0;
    if (i < 64 * 32) {
        int k = (i >> 5) + 1, l = i & 31;
        g_cosP[i] = make_float2((float)cos(TH * (double)k * (double)(l + 1)),
                                (float)cos(TH * (double)k * (double)(l + 33)));
    }
    if (i < 130) g_win[i] = (float)(0.5 - 0.5 * cos(TH * (double)i));
}

__global__ void zero_out_k(float4* __restrict__ out, int n4) {
    int i = blockIdx.x * blockDim.x + threadIdx.x;
    float4 z = make_float4(0.f, 0.f, 0.f, 0.f);
    for (; i < n4; i += gridDim.x * blockDim.x) out[i] = z;
}

__device__ __forceinline__ float msig(float x) {
    float sg = 1.0f / (1.0f + __expf(-x));
    return 2.0f * __powf(sg, 2.302585092994046f) + 1e-7f;
}

// ---------------- dynamic smem layout (bytes) ----------------
#define COS_OFF   0                      // float2[64*32]  = 16384
#define WIN_OFF   16384                  // float[130]     = 520 -> pad
#define SINT_OFF  16912                  // float[8][65][4]= 8320
#define XSB_OFF   25232                  // float[8][4][64]= 8192
#define WIR_OFF   33424                  // float[8][256]  = 8192
#define OUTB_OFF  41616                  // float[32][192] = 24576
#define SMEM_TOT  66192

__global__ __launch_bounds__(256) void fn_main(
        const float* __restrict__ coeff,   // (B, F, 65)
        const float* __restrict__ noise,   // (B, F, 64)
        float* __restrict__ out)           // (B, 262144)
{
    extern __shared__ __align__(16) char smdyn[];
    float2* cosP  = (float2*)(smdyn + COS_OFF);
    float*  winS  = (float*)(smdyn + WIN_OFF);
    float*  sIntF = (float*)(smdyn + SINT_OFF);   // [w][k][ff] : frame-interleaved msig(coeff)
    float*  xsb   = (float*)(smdyn + XSB_OFF);    // [w][ff][t]
    float*  wirb  = (float*)(smdyn + WIR_OFF);    // [w][256], zero-padded outside [64,192]
    float*  outb  = (float*)(smdyn + OUTB_OFF);   // [fi][192]

    const int tid = threadIdx.x;
    const int w   = tid >> 5;
    const int l   = tid & 31;
    const int q   = blockIdx.x;          // 0..127 (frames 0..4095; frame 4096 never contributes)
    const int b   = blockIdx.y;
    const int f0  = q * NFRB;

    // ---- stage tables + inputs ----
    for (int i = tid; i < 64 * 32; i += 256) cosP[i] = g_cosP[i];
    for (int i = tid; i < 130;     i += 256) winS[i] = g_win[i];
    for (int i = tid; i < NWARP * 256; i += 256) wirb[i] = 0.f;

    const size_t cb = ((size_t)b * F_ + f0) * FCL_;
    for (int e = tid; e < NFRB * FCL_; e += 256) {
        int fi = e / 65, k = e - fi * 65;
        sIntF[(((fi & 7) * 65) + k) * 4 + (fi >> 3)] = msig(coeff[cb + e]);
    }
    const size_t nb = ((size_t)b * F_ + f0) * FL_;
    for (int e = tid; e < NFRB * FL_; e += 256) {
        int fi = e >> 6, t = e & 63;
        xsb[((fi & 7) * 4 + (fi >> 3)) * 64 + t] = 2.f * noise[nb + e] - 1.f;
    }
    __syncthreads();

    // ---- cosine transform: 4 frames per warp jointly, packed f32x2 ----
    // zp[t] = (s0 + 2*sum_{k=1..64} s_k cos(2pi k t/129)) / 129 ; lane handles t1=l+1, t2=l+33
    const float* sw = sIntF + w * 65 * 4;
    ull ac0AB = 0, ac0CD = 0, ac1AB = 0, ac1CD = 0, ac2AB = 0, ac2CD = 0;
    const ULL2 s0p = *(const ULL2*)sw;               // (s0 of A,B) , (s0 of C,D)
    #pragma unroll 8
    for (int k = 1; k <= 64; k++) {
        const float2 ct = cosP[(k - 1) * 32 + l];
        const ULL2 sp = *(const ULL2*)(sw + k * 4);  // (skA,skB),(skC,skD)
        const ull c1d = dup_(ct.x), c2d = dup_(ct.y);
        ac1AB = fma2_(sp.x, c1d, ac1AB);  ac1CD = fma2_(sp.y, c1d, ac1CD);
        ac2AB = fma2_(sp.x, c2d, ac2AB);  ac2CD = fma2_(sp.y, c2d, ac2CD);
        ac0AB = add2_(ac0AB, sp.x);       ac0CD = add2_(ac0CD, sp.y);
    }
    const ull TWO = dup_(2.0f), SCL = dup_(1.0f / 129.0f);
    const ull zp0AB = mul2_(fma2_(ac0AB, TWO, s0p.x), SCL);
    const ull zp0CD = mul2_(fma2_(ac0CD, TWO, s0p.y), SCL);
    const ull zp1AB = mul2_(fma2_(ac1AB, TWO, s0p.x), SCL);
    const ull zp1CD = mul2_(fma2_(ac1CD, TWO, s0p.y), SCL);
    const ull zp2AB = mul2_(fma2_(ac2AB, TWO, s0p.x), SCL);
    const ull zp2CD = mul2_(fma2_(ac2CD, TWO, s0p.y), SCL);
    float zp0s[4], zp1s[4], zp2s[4];
    unpk_(zp0AB, zp0s[0], zp0s[1]); unpk_(zp0CD, zp0s[2], zp0s[3]);
    unpk_(zp1AB, zp1s[0], zp1s[1]); unpk_(zp1CD, zp1s[2], zp1s[3]);
    unpk_(zp2AB, zp2s[0], zp2s[1]); unpk_(zp2CD, zp2s[2], zp2s[3]);

    const int   t1  = l + 1,  t2 = l + 33;
    const float w1p = winS[64 + t1], w1m = winS[64 - t1];
    const float w2p = winS[64 + t2], w2m = winS[64 - t2];
    const float wc  = winS[64];
    const int   ll  = (l < 24) ? l : 0;      // conv uses 24 lanes x 8 outputs
    float* wb = wirb + w * 256;

    #pragma unroll
    for (int ff = 0; ff < 4; ff++) {
        const int fi = ff * NWARP + w;

        // windowed linear-phase IR: wb[128+/-t] = win * zp (zp even-symmetric)
        wb[128 + t1] = w1p * zp1s[ff];
        wb[128 - t1] = w1m * zp1s[ff];
        wb[128 + t2] = w2p * zp2s[ff];
        wb[128 - t2] = w2m * zp2s[ff];
        if (l == 0) wb[128] = wc * zp0s[ff];
        __syncwarp();

        // ---- conv: out[t]=sum_tau x[tau]*wb[64+t-tau], t=8*ll+c, sliding 12-float window ----
        const float* xs = xsb + (w * 4 + ff) * 64;
        ull acc0 = 0, acc1 = 0, acc2 = 0, acc3 = 0;
        const float* wp0 = wb + 60 + 8 * ll;        // window base for g=0 (16B aligned)
        ULL2 va = *(const ULL2*)(wp0);
        ULL2 vb = *(const ULL2*)(wp0 + 4);
        ULL2 vc = *(const ULL2*)(wp0 + 8);
        ull E0 = va.x, E1 = va.y, E2 = vb.x, E3 = vb.y, E4 = vc.x, E5 = vc.y;
        float f0v, f1v, f2v, f3v, f4v, f5v, f6v, f7v, f8v, f9v, f10v, f11v;
        unpk_(E0, f0v, f1v); unpk_(E1, f2v, f3v); unpk_(E2, f4v, f5v);
        unpk_(E3, f6v, f7v); unpk_(E4, f8v, f9v); unpk_(E5, f10v, f11v);
        ull O0 = pk_(f1v, f2v), O1 = pk_(f3v, f4v), O2 = pk_(f5v, f6v);
        ull O3 = pk_(f7v, f8v), O4 = pk_(f9v, f10v);
        float carry = f0v;

        #pragma unroll
        for (int g = 0; g < 16; g++) {
            const float4 xq = *(const float4*)(xs + 4 * g);
            const ull x0 = dup_(xq.x), x1 = dup_(xq.y), x2 = dup_(xq.z), x3 = dup_(xq.w);
            acc0 = fma2_(x0, E2, acc0); acc1 = fma2_(x0, E3, acc1);
            acc2 = fma2_(x0, E4, acc2); acc3 = fma2_(x0, E5, acc3);
            acc0 = fma2_(x1, O1, acc0); acc1 = fma2_(x1, O2, acc1);
            acc2 = fma2_(x1, O3, acc2); acc3 = fma2_(x1, O4, acc3);
            acc0 = fma2_(x2, E1, acc0); acc1 = fma2_(x2, E2, acc1);
            acc2 = fma2_(x2, E3, acc2); acc3 = fma2_(x2, E4, acc3);
            acc0 = fma2_(x3, O0, acc0); acc1 = fma2_(x3, O1, acc1);
            acc2 = fma2_(x3, O2, acc2); acc3 = fma2_(x3, O3, acc3);
            if (g < 15) {
                const ULL2 nw = *(const ULL2*)(wp0 - 4 * (g + 1));  // 4 new floats below
                float nf0, nf1, nf2, nf3;
                unpk_(nw.x, nf0, nf1); unpk_(nw.y, nf2, nf3);
                E5 = E3; E4 = E2; E3 = E1; E2 = E0; E1 = nw.y; E0 = nw.x;
                O4 = O2; O3 = O1; O2 = O0; O1 = pk_(nf3, carry); O0 = pk_(nf1, nf2);
                carry = nf0;
            }
        }
        if (l < 24) {
            ULL2* op = (ULL2*)(outb + fi * 192 + 8 * l);
            op[0] = ULL2{acc0, acc1};
            op[1] = ULL2{acc2, acc3};
        }
        __syncwarp();   // done with wb before next frame rewrites it
    }

    __syncthreads();

    // ---- overlap-add ----
    const size_t rowb = (size_t)b * OUT_S;
    const int gb = f0 * FL_;
    for (int p = tid; p < ACCLEN; p += 256) {
        const int P = gb + p;
        if (P >= OUT_S) continue;
        const int fhi = p >> 6;
        const int t0  = p & 63;
        float v = 0.f;
        if (fhi < NFRB)                 v += outb[fhi * 192 + t0];
        if (fhi >= 1 && fhi - 1 < NFRB) v += outb[(fhi - 1) * 192 + t0 + 64];
        if (fhi >= 2 && fhi - 2 < NFRB) v += outb[(fhi - 2) * 192 + t0 + 128];
        if (p >= 128 && p < 2048) out[rowb + P] = v;             // exclusively owned
        else                      atomicAdd(&out[rowb + P], v);  // block boundary
    }
}

extern "C" void kernel_launch(void* const* d_in, const int* in_sizes, int n_in,
                              void* d_out, int out_size) {
    const float* coeff = (const float*)d_in[0];
    const float* noise = (const float*)d_in[1];
    float* out = (float*)d_out;

    cudaFuncSetAttribute(fn_main, cudaFuncAttributeMaxDynamicSharedMemorySize, SMEM_TOT);
    init_tables_k<<<2, 1024>>>();
    zero_out_k<<<4096, 256>>>((float4*)out, (B_ * OUT_S) / 4);
    dim3 grid(128, B_);
    fn_main<<<grid, 256, SMEM_TOT>>>(coeff, noise, out);
}